// round 3
// baseline (speedup 1.0000x reference)
#include <cuda_runtime.h>
#include <cuda_bf16.h>
#include <cstdint>

// Dequant: out[r][c] = (float)q[r][c] * row_stats[r] * (1/127)
// ROWS = COLS = 8192, int32 in -> fp32 out. Pure streaming: 512 MiB total.
//
// R3: one block == one row. 256 threads x 8 int4 vecs = 2048 vecs = 8192 cols.
// Row scale loaded ONCE per block (uniform), so the hot path is pure
// LDG.E.128 (x8, front-batched, MLP=8) -> I2F+FMUL -> STG.E.128 (x8),
// all with streaming (.cs) cache hints.

#define VPT 8                         // int4 vectors per thread
#define TPB 256                       // threads per block
// TPB * VPT = 2048 int4 = 8192 int32 = one full row

__global__ void __launch_bounds__(TPB, 6)
dequant_kernel(const int4* __restrict__ q,
               const float* __restrict__ row_stats,
               float4* __restrict__ out)
{
    // Uniform per-block scale: block r handles row r.
    const float scale = __ldg(&row_stats[blockIdx.x]) * (1.0f / 127.0f);

    const int base = blockIdx.x * (TPB * VPT) + threadIdx.x;

    // Front-batch 8 independent LDG.E.128 (MLP=8).
    int4 v[VPT];
#pragma unroll
    for (int j = 0; j < VPT; j++)
        v[j] = __ldcs(&q[base + j * TPB]);

#pragma unroll
    for (int j = 0; j < VPT; j++) {
        float4 r;
        r.x = (float)v[j].x * scale;
        r.y = (float)v[j].y * scale;
        r.z = (float)v[j].z * scale;
        r.w = (float)v[j].w * scale;
        __stcs(&out[base + j * TPB], r);
    }
}

extern "C" void kernel_launch(void* const* d_in, const int* in_sizes, int n_in,
                              void* d_out, int out_size)
{
    const int4*  q         = (const int4*)d_in[0];   // int32 [8192,8192]
    const float* row_stats = (const float*)d_in[1];  // fp32  [8192]
    float4*      out       = (float4*)d_out;

    const int rows = in_sizes[1];                    // 8192 blocks, one per row

    dequant_kernel<<<rows, TPB>>>(q, row_stats, out);
}

// round 4
// speedup vs baseline: 1.0008x; 1.0008x over previous
#include <cuda_runtime.h>
#include <cuda_bf16.h>
#include <cstdint>

// Dequant: out[r][c] = (float)q[r][c] * row_stats[r] * (1/127)
// ROWS = COLS = 8192, int32 in -> fp32 out. Pure streaming: 512 MiB total.
//
// R4: contiguous-per-warp layout. One block == one row (256 thr x 8 int4 =
// 2048 vecs = 8192 cols). Each warp owns a contiguous 4 KB chunk of the row:
// its 8 front-batched LDG.E.128 hit back-to-back 512 B segments, so the
// in-flight loads (and the stores that follow) form long same-row,
// same-direction DRAM bursts instead of 8 scattered 4 KB-apart regions.
// Row scale uniform per block. Streaming (.cs) hints: zero reuse.

#define VPT 8                         // int4 vectors per thread
#define TPB 256                       // 8 warps; TPB*VPT = 2048 vecs = 1 row

__global__ void __launch_bounds__(TPB, 6)
dequant_kernel(const int4* __restrict__ q,
               const float* __restrict__ row_stats,
               float4* __restrict__ out)
{
    const float scale = __ldg(&row_stats[blockIdx.x]) * (1.0f / 127.0f);

    const int warp = threadIdx.x >> 5;
    const int lane = threadIdx.x & 31;

    // Warp w covers contiguous vecs [row*2048 + w*256, +256):
    // load j touches vecs [w*256 + j*32, +32)  -> sequential 512 B segments.
    const int base = blockIdx.x * (TPB * VPT) + warp * (32 * VPT) + lane;

    int4 v[VPT];
#pragma unroll
    for (int j = 0; j < VPT; j++)
        v[j] = __ldcs(&q[base + j * 32]);

#pragma unroll
    for (int j = 0; j < VPT; j++) {
        float4 r;
        r.x = (float)v[j].x * scale;
        r.y = (float)v[j].y * scale;
        r.z = (float)v[j].z * scale;
        r.w = (float)v[j].w * scale;
        __stcs(&out[base + j * 32], r);
    }
}

extern "C" void kernel_launch(void* const* d_in, const int* in_sizes, int n_in,
                              void* d_out, int out_size)
{
    const int4*  q         = (const int4*)d_in[0];   // int32 [8192,8192]
    const float* row_stats = (const float*)d_in[1];  // fp32  [8192]
    float4*      out       = (float4*)d_out;

    const int rows = in_sizes[1];                    // 8192 blocks, one per row

    dequant_kernel<<<rows, TPB>>>(q, row_stats, out);
}